// round 15
// baseline (speedup 1.0000x reference)
#include <cuda_runtime.h>
#include <stdint.h>

#define NUM_BINS 256
#define NCH_SAMPLE 3
#define NCH_TOTAL 6
#define NPX (2048 * 4096)

#define SLICES 197                  // hist slices per channel
#define NHIST (SLICES * 3)          // 591 hist CTAs (<= 148 SMs * 4 smem slots)
#define NCOPY 592                   // pure-copy CTAs (no smem, no sync)
#define NCTAS (NHIST + NCOPY)
#define GPC 10646                   // float4 groups per hist CTA

// Static device scratch (zeroed at load; last-done hist CTA restores zeros
// each run, so graph replays are deterministic).
__device__ int g_hist[NCH_SAMPLE][NUM_BINS];
__device__ int g_ticket;
__device__ int g_done;

// Heterogeneous persistent kernel:
//  blocks [0, NHIST):   A hist+binize own sample slice (bins in smem)
//                       C spin on ticket -> LUT ; D apply -> output
//  blocks [NHIST, ...): pure streaming copy of target channels. These CTAs
//                       co-reside with hist CTAs (no smem) and keep DRAM
//                       saturated while hist warps throttle on the smem
//                       crossbar and during the sync tail. They exit, so
//                       queued hist CTAs always eventually get slots.
__global__ void __launch_bounds__(256, 4)
equalize_fused_kernel(const float* __restrict__ img,
                      float* __restrict__ out, int npx) {
    const int t = threadIdx.x;
    const int n4 = npx >> 2;

    // ───────── copy CTAs ─────────
    if (blockIdx.x >= NHIST) {
        const int cb = blockIdx.x - NHIST;
        const float4* p = (const float4*)(img + (size_t)NCH_SAMPLE * npx);
        float4*       q = (float4*)(out + (size_t)NCH_SAMPLE * npx);
        const int tn4 = NCH_SAMPLE * n4;
        const int stride = NCOPY * 256;
        int i = cb * 256 + t;
        for (; i + stride < tn4; i += 2 * stride) {
            float4 a = __ldcs(&p[i]);
            float4 d = __ldcs(&p[i + stride]);
            __stcs(&q[i], a);
            __stcs(&q[i + stride], d);
        }
        if (i < tn4) __stcs(&q[i], __ldcs(&p[i]));
        return;
    }

    // ───────── hist/apply CTAs ─────────
    const int c  = blockIdx.x % NCH_SAMPLE;     // channel
    const int sl = blockIdx.x / NCH_SAMPLE;     // slice within channel
    const int base = sl * GPC;
    const int end  = min(base + GPC, n4);

    __shared__ uint32_t s_bins[GPC];            // 42584 B packed bins
    __shared__ int      s_hist[4][NUM_BINS];    // 4 KB replicas / scan scratch
    __shared__ float    s_lut[NUM_BINS];        // 1 KB
    __shared__ int      s_lastnz;

    for (int i = t; i < 4 * NUM_BINS; i += blockDim.x) ((int*)s_hist)[i] = 0;
    __syncthreads();

    // ---- Phase A: hist + binize (sample read happens exactly once) ----
    {
        const float4* p = (const float4*)(img + (size_t)c * npx);
        const int sub = t & 3;
        for (int g = base + t; g < end; g += 256) {
            float4 v = __ldcs(&p[g]);
            int b0 = min(255, max(0, (int)v.x));
            int b1 = min(255, max(0, (int)v.y));
            int b2 = min(255, max(0, (int)v.z));
            int b3 = min(255, max(0, (int)v.w));
            s_bins[g - base] = (uint32_t)b0 | ((uint32_t)b1 << 8) |
                               ((uint32_t)b2 << 16) | ((uint32_t)b3 << 24);
            atomicAdd(&s_hist[sub][b0], 1);
            atomicAdd(&s_hist[sub][b1], 1);
            atomicAdd(&s_hist[sub][b2], 1);
            atomicAdd(&s_hist[sub][b3], 1);
        }
    }
    __syncthreads();
    {
        int s = s_hist[0][t] + s_hist[1][t] + s_hist[2][t] + s_hist[3][t];
        if (s) atomicAdd(&g_hist[c][t], s);
    }
    __threadfence();                            // release hist before arrive
    if (t == 0) atomicAdd(&g_ticket, 1);

    // ---- Phase C: wait for all hist arrivals, then build this channel's LUT
    if (t == 0) {
        while (*(volatile int*)&g_ticket != NHIST) __nanosleep(128);
    }
    __syncthreads();
    __threadfence();

    {
        int* hist = s_hist[0];
        int* cum  = s_hist[1];
        int h = __ldcg(&g_hist[c][t]);
        hist[t] = h;
        cum[t]  = h;
        if (t == 0) s_lastnz = 0;
        __syncthreads();

        #pragma unroll
        for (int off = 1; off < NUM_BINS; off <<= 1) {
            int tmp = (t >= off) ? cum[t - off] : 0;
            __syncthreads();
            cum[t] += tmp;
            __syncthreads();
        }
        if (h > 0) atomicMax(&s_lastnz, t);
        __syncthreads();

        const int total = cum[NUM_BINS - 1];
        const int step  = (total - hist[s_lastnz]) / (NUM_BINS - 1);

        float outv;
        if (step == 0) {
            outv = (float)t;                    // identity when step==0
        } else {
            int l = (t == 0) ? 0 : (cum[t - 1] + (step >> 1)) / step;
            outv = (float)min(NUM_BINS - 1, max(0, l));
        }
        s_lut[t] = outv;
        __syncthreads();
    }

    // ---- Phase D: apply from smem bins (no global re-read of samples) ----
    {
        float4* q = (float4*)(out + (size_t)c * npx);
        for (int g = base + t; g < end; g += 256) {
            uint32_t w = s_bins[g - base];
            float4 r;
            r.x = s_lut[w & 255];
            r.y = s_lut[(w >> 8) & 255];
            r.z = s_lut[(w >> 16) & 255];
            r.w = s_lut[w >> 24];
            __stcs(&q[g], r);
        }
    }

    // ---- reset shared state for next graph replay (last-done hist CTA) ----
    __syncthreads();
    __shared__ int s_last;
    if (t == 0) {
        int d = atomicAdd(&g_done, 1);
        s_last = (d == NHIST - 1);
    }
    __syncthreads();
    if (s_last) {
        g_hist[0][t] = 0;
        g_hist[1][t] = 0;
        g_hist[2][t] = 0;
        if (t == 0) { g_ticket = 0; g_done = 0; }
    }
}

extern "C" void kernel_launch(void* const* d_in, const int* in_sizes, int n_in,
                              void* d_out, int out_size) {
    const float* img = (const float*)d_in[0];
    float* out = (float*)d_out;
    const int npx = in_sizes[0] / NCH_TOTAL;   // 2048*4096

    equalize_fused_kernel<<<NCTAS, 256>>>(img, out, npx);
}

// round 16
// speedup vs baseline: 1.0427x; 1.0427x over previous
#include <cuda_runtime.h>
#include <stdint.h>

#define NUM_BINS 256
#define NCH_SAMPLE 3
#define NCH_TOTAL 6
#define NPX (2048 * 4096)

#define SLICES 197                 // slices per channel
#define NCTAS (SLICES * 3)         // 591 CTAs total (<= 148 SMs * 4 resident)
#define GPC 10646                  // float4 groups per CTA: ceil(2097152/197)

// Static device scratch (zeroed at load; last-done CTA restores zeros each
// run, so graph replays are deterministic).
__device__ int g_hist[NCH_SAMPLE][NUM_BINS];
__device__ int g_ticket;
__device__ int g_done;

// Single persistent kernel, crossbar work moved under the copy stream:
//  A : read own sample slice once, convert, store packed bins to smem.
//      NO atomics -> runs at DRAM cap.
//  B1: histogram from s_bins (2 words + 8 smem atomics per iter, crossbar)
//      interleaved 2:1 with target copy (DRAM) until hist done -> ticket.
//  B2: pure copy remainder (hides other CTAs' B1 + the spin).
//  C : spin on ticket, build own channel's LUT.
//  D : apply LUT from smem bins -> output.
__global__ void __launch_bounds__(256, 4)
equalize_fused_kernel(const float* __restrict__ img,
                      float* __restrict__ out, int npx) {
    const int t = threadIdx.x;
    const int c  = blockIdx.x % NCH_SAMPLE;     // channel
    const int sl = blockIdx.x / NCH_SAMPLE;     // slice within channel
    const int n4 = npx >> 2;
    const int base = sl * GPC;
    const int end  = min(base + GPC, n4);

    __shared__ uint32_t s_bins[GPC];            // 42584 B packed bins
    __shared__ int      s_hist[4][NUM_BINS];    // 4 KB replicas / scan scratch
    __shared__ float    s_lut[NUM_BINS];        // 1 KB
    __shared__ int      s_lastnz;

    for (int i = t; i < 4 * NUM_BINS; i += blockDim.x) ((int*)s_hist)[i] = 0;
    __syncthreads();

    // ---- Phase A: read + convert + store bins (no atomics) ----
    {
        const float4* p = (const float4*)(img + (size_t)c * npx);
        for (int g = base + t; g < end; g += 256) {
            float4 v = __ldcs(&p[g]);
            int b0 = min(255, max(0, (int)v.x));
            int b1 = min(255, max(0, (int)v.y));
            int b2 = min(255, max(0, (int)v.z));
            int b3 = min(255, max(0, (int)v.w));
            s_bins[g - base] = (uint32_t)b0 | ((uint32_t)b1 << 8) |
                               ((uint32_t)b2 << 16) | ((uint32_t)b3 << 24);
        }
    }
    __syncthreads();

    const float4* cp = (const float4*)(img + (size_t)NCH_SAMPLE * npx);
    float4*       cq = (float4*)(out + (size_t)NCH_SAMPLE * npx);
    const int tn4 = NCH_SAMPLE * n4;
    const int cstride = NCTAS * 256;
    int ci = blockIdx.x * 256 + t;

    // ---- Phase B1: histogram from s_bins (crossbar) under copy (DRAM) ----
    {
        const int sub = t & 3;
        int gi = base + t;
        for (; gi + 256 < end; gi += 512) {
            uint32_t w0 = s_bins[gi - base];
            uint32_t w1 = s_bins[gi - base + 256];
            float4 a;
            const bool cv = ci < tn4;
            if (cv) a = __ldcs(&cp[ci]);        // DRAM load in flight
            atomicAdd(&s_hist[sub][w0 & 255], 1);
            atomicAdd(&s_hist[sub][(w0 >> 8) & 255], 1);
            atomicAdd(&s_hist[sub][(w0 >> 16) & 255], 1);
            atomicAdd(&s_hist[sub][w0 >> 24], 1);
            atomicAdd(&s_hist[sub][w1 & 255], 1);
            atomicAdd(&s_hist[sub][(w1 >> 8) & 255], 1);
            atomicAdd(&s_hist[sub][(w1 >> 16) & 255], 1);
            atomicAdd(&s_hist[sub][w1 >> 24], 1);
            if (cv) { __stcs(&cq[ci], a); ci += cstride; }
        }
        if (gi < end) {
            uint32_t w = s_bins[gi - base];
            atomicAdd(&s_hist[sub][w & 255], 1);
            atomicAdd(&s_hist[sub][(w >> 8) & 255], 1);
            atomicAdd(&s_hist[sub][(w >> 16) & 255], 1);
            atomicAdd(&s_hist[sub][w >> 24], 1);
        }
    }
    __syncthreads();
    {
        int s = s_hist[0][t] + s_hist[1][t] + s_hist[2][t] + s_hist[3][t];
        if (s) atomicAdd(&g_hist[c][t], s);
    }
    __threadfence();                            // release hist before arrive
    if (t == 0) atomicAdd(&g_ticket, 1);

    // ---- Phase B2: pure copy remainder (hides the sync) ----
    for (; ci + cstride < tn4; ci += 2 * cstride) {
        float4 a = __ldcs(&cp[ci]);
        float4 d = __ldcs(&cp[ci + cstride]);
        __stcs(&cq[ci], a);
        __stcs(&cq[ci + cstride], d);
    }
    if (ci < tn4) __stcs(&cq[ci], __ldcs(&cp[ci]));

    // ---- Phase C: wait for all hist arrivals, then build this channel's LUT
    if (t == 0) {
        while (*(volatile int*)&g_ticket != NCTAS) __nanosleep(128);
    }
    __syncthreads();
    __threadfence();

    {
        int* hist = s_hist[0];
        int* cum  = s_hist[1];
        int h = __ldcg(&g_hist[c][t]);
        hist[t] = h;
        cum[t]  = h;
        if (t == 0) s_lastnz = 0;
        __syncthreads();

        #pragma unroll
        for (int off = 1; off < NUM_BINS; off <<= 1) {
            int tmp = (t >= off) ? cum[t - off] : 0;
            __syncthreads();
            cum[t] += tmp;
            __syncthreads();
        }
        if (h > 0) atomicMax(&s_lastnz, t);
        __syncthreads();

        const int total = cum[NUM_BINS - 1];
        const int step  = (total - hist[s_lastnz]) / (NUM_BINS - 1);

        float outv;
        if (step == 0) {
            outv = (float)t;                    // identity when step==0
        } else {
            int l = (t == 0) ? 0 : (cum[t - 1] + (step >> 1)) / step;
            outv = (float)min(NUM_BINS - 1, max(0, l));
        }
        s_lut[t] = outv;
        __syncthreads();
    }

    // ---- Phase D: apply from smem bins (no global re-read of samples) ----
    {
        float4* q = (float4*)(out + (size_t)c * npx);
        for (int g = base + t; g < end; g += 256) {
            uint32_t w = s_bins[g - base];
            float4 r;
            r.x = s_lut[w & 255];
            r.y = s_lut[(w >> 8) & 255];
            r.z = s_lut[(w >> 16) & 255];
            r.w = s_lut[w >> 24];
            __stcs(&q[g], r);
        }
    }

    // ---- reset shared state for next graph replay (last-done CTA) ----
    __syncthreads();
    __shared__ int s_last;
    if (t == 0) {
        int d = atomicAdd(&g_done, 1);
        s_last = (d == NCTAS - 1);
    }
    __syncthreads();
    if (s_last) {
        g_hist[0][t] = 0;
        g_hist[1][t] = 0;
        g_hist[2][t] = 0;
        if (t == 0) { g_ticket = 0; g_done = 0; }
    }
}

extern "C" void kernel_launch(void* const* d_in, const int* in_sizes, int n_in,
                              void* d_out, int out_size) {
    const float* img = (const float*)d_in[0];
    float* out = (float*)d_out;
    const int npx = in_sizes[0] / NCH_TOTAL;   // 2048*4096

    equalize_fused_kernel<<<NCTAS, 256>>>(img, out, npx);
}

// round 17
// speedup vs baseline: 1.1107x; 1.0652x over previous
#include <cuda_runtime.h>
#include <stdint.h>

#define NUM_BINS 256
#define NCH_SAMPLE 3
#define NCH_TOTAL 6
#define NPX (2048 * 4096)

#define SLICES 197                 // slices per channel
#define NCTAS (SLICES * 3)         // 591 CTAs total (<= 148 SMs * 4 resident)
#define GPC 10646                  // float4 groups per CTA: ceil(2097152/197)

// Static device scratch (zeroed at load; last-done CTA restores zeros each
// run, so graph replays are deterministic).
__device__ int g_hist[NCH_SAMPLE][NUM_BINS];
__device__ int g_ticket[NCH_SAMPLE];
__device__ int g_done;

// Single persistent kernel (R10/R12 proven structure + per-channel tickets):
//  A: hist + binize own sample slice (bins kept in smem), arrive on own
//     channel's ticket IMMEDIATELY after the hist flush.
//  B: grid-stride copy of target channels (buries the sync wait).
//  C: spin on own channel's ticket (197 arrivals, not 591), build LUT.
//  D: apply LUT from smem bins -> output.
__global__ void __launch_bounds__(256, 4)
equalize_fused_kernel(const float* __restrict__ img,
                      float* __restrict__ out, int npx) {
    const int t = threadIdx.x;
    const int c  = blockIdx.x % NCH_SAMPLE;     // channel
    const int sl = blockIdx.x / NCH_SAMPLE;     // slice within channel
    const int n4 = npx >> 2;
    const int base = sl * GPC;
    const int end  = min(base + GPC, n4);

    __shared__ uint32_t s_bins[GPC];            // 42584 B packed bins
    __shared__ int      s_hist[4][NUM_BINS];    // 4 KB replicas / scan scratch
    __shared__ float    s_lut[NUM_BINS];        // 1 KB
    __shared__ int      s_lastnz;

    // ---- Phase A: hist + binize (sample read happens exactly once) ----
    for (int i = t; i < 4 * NUM_BINS; i += blockDim.x) ((int*)s_hist)[i] = 0;
    __syncthreads();

    {
        const float4* p = (const float4*)(img + (size_t)c * npx);
        const int sub = t & 3;
        for (int g = base + t; g < end; g += 256) {
            float4 v = __ldcs(&p[g]);
            int b0 = min(255, max(0, (int)v.x));
            int b1 = min(255, max(0, (int)v.y));
            int b2 = min(255, max(0, (int)v.z));
            int b3 = min(255, max(0, (int)v.w));
            s_bins[g - base] = (uint32_t)b0 | ((uint32_t)b1 << 8) |
                               ((uint32_t)b2 << 16) | ((uint32_t)b3 << 24);
            atomicAdd(&s_hist[sub][b0], 1);
            atomicAdd(&s_hist[sub][b1], 1);
            atomicAdd(&s_hist[sub][b2], 1);
            atomicAdd(&s_hist[sub][b3], 1);
        }
    }
    __syncthreads();
    {
        int s = s_hist[0][t] + s_hist[1][t] + s_hist[2][t] + s_hist[3][t];
        if (s) atomicAdd(&g_hist[c][t], s);
    }
    __threadfence();                            // release hist before arrive
    if (t == 0) atomicAdd(&g_ticket[c], 1);     // arrive EARLY (own channel)

    // ---- Phase B: target copy (buries the sync wait) ----
    {
        const float4* p = (const float4*)(img + (size_t)NCH_SAMPLE * npx);
        float4*       q = (float4*)(out + (size_t)NCH_SAMPLE * npx);
        const int tn4 = NCH_SAMPLE * n4;
        const int stride = NCTAS * 256;
        int i = blockIdx.x * 256 + t;
        for (; i + stride < tn4; i += 2 * stride) {
            float4 a = __ldcs(&p[i]);
            float4 d = __ldcs(&p[i + stride]);
            __stcs(&q[i], a);
            __stcs(&q[i + stride], d);
        }
        if (i < tn4) __stcs(&q[i], __ldcs(&p[i]));
    }

    // ---- Phase C: wait for OWN channel's arrivals, then build the LUT ----
    if (t == 0) {
        while (*(volatile int*)&g_ticket[c] != SLICES) __nanosleep(32);
    }
    __syncthreads();
    __threadfence();

    {
        int* hist = s_hist[0];
        int* cum  = s_hist[1];
        int h = __ldcg(&g_hist[c][t]);
        hist[t] = h;
        cum[t]  = h;
        if (t == 0) s_lastnz = 0;
        __syncthreads();

        #pragma unroll
        for (int off = 1; off < NUM_BINS; off <<= 1) {
            int tmp = (t >= off) ? cum[t - off] : 0;
            __syncthreads();
            cum[t] += tmp;
            __syncthreads();
        }
        if (h > 0) atomicMax(&s_lastnz, t);
        __syncthreads();

        const int total = cum[NUM_BINS - 1];
        const int step  = (total - hist[s_lastnz]) / (NUM_BINS - 1);

        float outv;
        if (step == 0) {
            outv = (float)t;                    // identity when step==0
        } else {
            int l = (t == 0) ? 0 : (cum[t - 1] + (step >> 1)) / step;
            outv = (float)min(NUM_BINS - 1, max(0, l));
        }
        s_lut[t] = outv;
        __syncthreads();
    }

    // ---- Phase D: apply from smem bins (no global re-read of samples) ----
    {
        float4* q = (float4*)(out + (size_t)c * npx);
        for (int g = base + t; g < end; g += 256) {
            uint32_t w = s_bins[g - base];
            float4 r;
            r.x = s_lut[w & 255];
            r.y = s_lut[(w >> 8) & 255];
            r.z = s_lut[(w >> 16) & 255];
            r.w = s_lut[w >> 24];
            __stcs(&q[g], r);
        }
    }

    // ---- reset shared state for next graph replay (last-done CTA) ----
    __syncthreads();
    __shared__ int s_last;
    if (t == 0) {
        int d = atomicAdd(&g_done, 1);
        s_last = (d == NCTAS - 1);
    }
    __syncthreads();
    if (s_last) {
        g_hist[0][t] = 0;
        g_hist[1][t] = 0;
        g_hist[2][t] = 0;
        if (t == 0) {
            g_ticket[0] = 0; g_ticket[1] = 0; g_ticket[2] = 0;
            g_done = 0;
        }
    }
}

extern "C" void kernel_launch(void* const* d_in, const int* in_sizes, int n_in,
                              void* d_out, int out_size) {
    const float* img = (const float*)d_in[0];
    float* out = (float*)d_out;
    const int npx = in_sizes[0] / NCH_TOTAL;   // 2048*4096

    equalize_fused_kernel<<<NCTAS, 256>>>(img, out, npx);
}